// round 7
// baseline (speedup 1.0000x reference)
#include <cuda_runtime.h>
#include <cstdint>

#define BB 16
#define VV 8
#define SS 256
#define KK 66
#define NSEQ (BB*VV)   // 128

__device__ float g_part[NSEQ];

// ---------------- argmax over last dim of log_pa (B,S,S,K) ----------------
// Warp per row, 4 rows per iteration for MLP. 277MB stream -> HBM-bound.
// First-occurrence tie-break (matches jnp.argmax) via second min-reduce.
__global__ void __launch_bounds__(256) argmax_kernel(const float* __restrict__ lp,
                                                     float* __restrict__ out)
{
    const int ROWS = BB * SS * SS;          // 1,048,576
    const int lane  = threadIdx.x & 31;
    const int gwarp = (blockIdx.x * blockDim.x + threadIdx.x) >> 5;
    const int nwarp = (gridDim.x * blockDim.x) >> 5;

    for (int base = gwarp * 4; base < ROWS; base += nwarp * 4) {
        float best[4]; int bi[4];
#pragma unroll
        for (int r = 0; r < 4; ++r) {
            const float* p = lp + (size_t)(base + r) * KK + lane;
            float v0 = __ldg(p);
            float v1 = __ldg(p + 32);
            best[r] = v0; bi[r] = lane;
            if (v1 > best[r]) { best[r] = v1; bi[r] = lane + 32; }
            if (lane < 2) {
                float v2 = __ldg(p + 64);
                if (v2 > best[r]) { best[r] = v2; bi[r] = lane + 64; }
            }
        }
#pragma unroll
        for (int r = 0; r < 4; ++r) {
            // monotonic key for float compare via integer max
            unsigned kb = __float_as_uint(best[r]);
            kb = (kb & 0x80000000u) ? ~kb : (kb | 0x80000000u);
            unsigned kmax = __reduce_max_sync(0xffffffffu, kb);
            // first-occurrence tie-break: min index among lanes holding kmax
            unsigned cand = (kb == kmax) ? (unsigned)bi[r] : 0xffffffffu;
            unsigned imin = __reduce_min_sync(0xffffffffu, cand);
            if (lane == 0) out[base + r] = (float)imin;
        }
    }
}

// ---------------- CRF per-sequence kernel ----------------
// One block per sequence n = b*V + v. Exp-domain alpha recurrence with
// exp(trans) column held in registers, exp(score) staged in dynamic smem,
// renormalization (max) every 4 steps.
__global__ void __launch_bounds__(128, 1) crf_kernel(
    const float* __restrict__ score,       // (B,S,S,K)
    const int*   __restrict__ v_label,     // (B,V)
    const int*   __restrict__ orig_l,      // (B,)
    const int*   __restrict__ role_label,  // (B,V,S)
    const float* __restrict__ start_t,     // (K,)
    const float* __restrict__ trans,       // (K,K)
    const float* __restrict__ end_t)       // (K,)
{
    extern __shared__ float sE[];          // S*K floats = exp(a_score)
    __shared__ __align__(16) float sA[2][68];
    __shared__ int   sTag[SS];
    __shared__ float sRed[128];
    __shared__ float sScale[2];            // [0]=1/m, [1]=log(m)

    const int tid = threadIdx.x;
    const int n = blockIdx.x;
    const int b = n >> 3;                  // / VV
    const int qrow = v_label[n];
    const int L = orig_l[b];               // prefix mask length, >= S/2 >= 2
    const float* asc = score + ((size_t)b * SS + qrow) * SS * KK;  // a_score[t*K + j]

    // tags (only t < L needed) + alpha padding init
    for (int t = tid; t < L; t += 128) sTag[t] = role_label[(size_t)n * SS + t];
    if (tid < 2) { sA[0][66 + tid] = 0.f; sA[1][66 + tid] = 0.f; }
    __syncthreads();

    // stage E = exp(a_score) into smem; fold emission numerator into the pass
    float acc = 0.f;
    const int total = L * KK;
    for (int idx = tid; idx < total; idx += 128) {
        int t = idx / KK;
        int j = idx - t * KK;
        float val = __ldg(asc + idx);
        sE[idx] = __expf(val);
        if (j == sTag[t]) acc += val;      // emit[t] = a_score[t, tag_t]
    }
    // transition numerator: sum_{t=1}^{L-1} trans[tag_{t-1}, tag_t]
    for (int t = tid + 1; t < L; t += 128)
        acc += __ldg(trans + sTag[t - 1] * KK + sTag[t]);
    sRed[tid] = acc;

    // exp(trans) column j into registers (constant across time)
    float Tc[68];
#pragma unroll
    for (int i = 0; i < 66; ++i)
        Tc[i] = (tid < 66) ? __expf(__ldg(trans + i * KK + tid)) : 0.f;
    Tc[66] = 0.f; Tc[67] = 0.f;

    __syncthreads();
    // deterministic tree reduction of the numerator
    for (int s = 64; s > 0; s >>= 1) {
        if (tid < s) sRed[tid] += sRed[tid + s];
        __syncthreads();
    }
    float numer = 0.f;
    if (tid == 0)
        numer = sRed[0] + __ldg(start_t + sTag[0]) + __ldg(end_t + sTag[L - 1]);

    // alpha0 (exp domain): A[j] = exp(start_t[j]) * E[0][j]
    if (tid < 66) sA[0][tid] = __expf(start_t[tid]) * sE[tid];
    __syncthreads();

    float Cl = 0.f;                        // accumulated log-scale
    int cur = 0;
    for (int t = 1; t < L; ++t) {
        float inv = 1.f;
        if ((t & 3) == 0) {                // renormalize current alpha before use
            if (tid < 32) {
                float m = fmaxf(sA[cur][tid], sA[cur][tid + 32]);
                if (tid < 2) m = fmaxf(m, sA[cur][tid + 64]);
#pragma unroll
                for (int off = 16; off > 0; off >>= 1)
                    m = fmaxf(m, __shfl_down_sync(0xffffffffu, m, off));
                if (tid == 0) { sScale[0] = 1.f / m; sScale[1] = __logf(m); }
            }
            __syncthreads();
            inv = sScale[0];
            Cl += sScale[1];
        }
        if (tid < 66) {
            const float4* A4 = (const float4*)sA[cur];
            float a0 = 0.f, a1 = 0.f, a2 = 0.f, a3 = 0.f;
#pragma unroll
            for (int ii = 0; ii < 17; ++ii) {
                float4 a = A4[ii];
                a0 = fmaf(a.x, Tc[4 * ii + 0], a0);
                a1 = fmaf(a.y, Tc[4 * ii + 1], a1);
                a2 = fmaf(a.z, Tc[4 * ii + 2], a2);
                a3 = fmaf(a.w, Tc[4 * ii + 3], a3);
            }
            float s = (a0 + a1) + (a2 + a3);
            sA[cur ^ 1][tid] = s * inv * sE[t * KK + tid];
        }
        __syncthreads();
        cur ^= 1;
    }

    // log_z = Cl + log( sum_j A[j] * exp(end_t[j]) )
    float val = 0.f;
    if (tid < 66) val = sA[cur][tid] * __expf(end_t[tid]);
    sRed[tid] = val;
    __syncthreads();
    for (int s = 64; s > 0; s >>= 1) {
        if (tid < s) sRed[tid] += sRed[tid + s];
        __syncthreads();
    }
    if (tid == 0) {
        float logz = Cl + __logf(sRed[0]);
        g_part[n] = numer - logz;
    }
}

// ---------------- finalize: loss = sum(g_part) / (B*V) ----------------
__global__ void finalize_kernel(float* __restrict__ out)
{
    __shared__ float s[128];
    const int tid = threadIdx.x;
    s[tid] = g_part[tid];
    __syncthreads();
    for (int st = 64; st > 0; st >>= 1) {
        if (tid < st) s[tid] += s[tid + st];
        __syncthreads();
    }
    if (tid == 0) out[0] = s[0] / (float)NSEQ;
}

extern "C" void kernel_launch(void* const* d_in, const int* in_sizes, int n_in,
                              void* d_out, int out_size)
{
    (void)in_sizes; (void)n_in; (void)out_size;
    const float* log_pa     = (const float*)d_in[0];
    const float* score      = (const float*)d_in[1];
    const int*   v_label    = (const int*)d_in[2];
    // d_in[3] = v_l (unused by reference)
    const int*   orig_l     = (const int*)d_in[4];
    const int*   role_label = (const int*)d_in[5];
    const float* start_t    = (const float*)d_in[6];
    const float* trans      = (const float*)d_in[7];
    const float* end_t      = (const float*)d_in[8];
    float* out = (float*)d_out;

    // opt-in for >48KB dynamic smem (idempotent; not an allocation)
    cudaFuncSetAttribute((const void*)crf_kernel,
                         cudaFuncAttributeMaxDynamicSharedMemorySize,
                         SS * KK * (int)sizeof(float));

    crf_kernel<<<NSEQ, 128, SS * KK * sizeof(float)>>>(
        score, v_label, orig_l, role_label, start_t, trans, end_t);
    argmax_kernel<<<2048, 256>>>(log_pa, out + 1);
    finalize_kernel<<<1, 128>>>(out);
}